// round 1
// baseline (speedup 1.0000x reference)
#include <cuda_runtime.h>
#include <cstdint>

#define NVT 20000      // total voxels
#define NVR 8000       // roi voxels
#define COUT 960       // 64+128+256+512
#define BATCH 8

// Normalized roi indices (int32), filled by prep kernel.
__device__ int g_roi[NVR];

// roi_idx may arrive as int64 (reference uses jnp.int64) or int32.
// Heuristic: view as int32; if the first 8 odd words are all zero, the data is
// little-endian int64 (high halves of values < 20000). Sorted random indices
// make 8 consecutive odd-position int32 values all-zero essentially impossible.
__global__ void prep_roi_kernel(const void* __restrict__ roi_raw) {
    int i = blockIdx.x * blockDim.x + threadIdx.x;
    if (i >= NVR) return;
    const int* p32 = (const int*)roi_raw;
    bool is64 = true;
#pragma unroll
    for (int j = 0; j < 8; j++) is64 = is64 && (p32[2 * j + 1] == 0);
    int v;
    if (is64) v = (int)((const long long*)roi_raw)[i];
    else      v = p32[i];
    g_roi[i] = v;
}

struct Params {
    const float* fmap[4];
    const float* rf[4];
    const float* w[4];
    int K[4];
    int Cmask[4];
    int Cshift[4];
    int chan_off[4];
    int mstart[4];
};

// Fused per-layer SGEMM: out[b, coff+c, v] = (fmap[b,c,:] . lrelu(rf[:,roi[v]])) * w[c,roi[v]]
// Tile: 128(M) x 128(N) x 16(K), 256 threads, 8x8 per-thread micro-tile.
__global__ __launch_bounds__(256, 2)
void fused_layer_gemm(Params prm, float* __restrict__ out)
{
    __shared__ float As[16][132];   // padded: conflict-free transpose stores
    __shared__ float Bs[16][128];
    __shared__ int   roi_s[128];

    const int nt = blockIdx.x;
    const int my = blockIdx.y;
    const int layer = (my >= 28) ? 3 : (my >= 12) ? 2 : (my >= 4) ? 1 : 0;

    const float* __restrict__ fmap = prm.fmap[layer];
    const float* __restrict__ rf   = prm.rf[layer];
    const float* __restrict__ w    = prm.w[layer];
    const int K      = prm.K[layer];
    const int Cmask  = prm.Cmask[layer];
    const int Cshift = prm.Cshift[layer];
    const int coff   = prm.chan_off[layer];
    const int mtile  = my - prm.mstart[layer];

    const int m0 = mtile * 128;
    const int n0 = nt * 128;
    const int tid = threadIdx.x;

    if (tid < 128) {
        int v = n0 + tid;
        roi_s[tid] = (v < NVR) ? g_roi[v] : 0;
    }
    __syncthreads();

    const int tm = tid >> 4, tn = tid & 15;
    const int mbase = tm * 8, nbase = tn * 8;

    // A-load mapping: 4 threads x 4 floats cover one 16-float k-row; 64 rows/pass, 2 passes.
    const int ar = tid >> 2;
    const int ak = (tid & 3) << 2;
    // B-load mapping: 128 threads across v, 2 k-rows per pass, 8 passes.
    const int bv = tid & 127;
    const int bk = tid >> 7;
    const int roi_v = roi_s[bv];
    const bool kvec = (K & 3) == 0;   // float4 A loads safe (fails only for K=49)

    float acc[8][8];
#pragma unroll
    for (int i = 0; i < 8; i++)
#pragma unroll
        for (int j = 0; j < 8; j++) acc[i][j] = 0.f;

    for (int k0 = 0; k0 < K; k0 += 16) {
        // ---- load A tile (transposed into smem) ----
#pragma unroll
        for (int h = 0; h < 2; h++) {
            int m = m0 + ar + h * 64;
            int k = k0 + ak;
            float a0 = 0.f, a1 = 0.f, a2 = 0.f, a3 = 0.f;
            const float* ap = fmap + (size_t)m * K + k;
            if (kvec && k + 4 <= K) {
                float4 t = *(const float4*)ap;
                a0 = t.x; a1 = t.y; a2 = t.z; a3 = t.w;
            } else {
                if (k + 0 < K) a0 = ap[0];
                if (k + 1 < K) a1 = ap[1];
                if (k + 2 < K) a2 = ap[2];
                if (k + 3 < K) a3 = ap[3];
            }
            As[ak + 0][ar + h * 64] = a0;
            As[ak + 1][ar + h * 64] = a1;
            As[ak + 2][ar + h * 64] = a2;
            As[ak + 3][ar + h * 64] = a3;
        }
        // ---- load B tile: gather + leaky_relu ----
#pragma unroll
        for (int j = 0; j < 8; j++) {
            int kr = bk + 2 * j;
            int k = k0 + kr;
            float bval = 0.f;
            if (k < K) {
                bval = __ldg(rf + (size_t)k * NVT + roi_v);
                bval = (bval > 0.f) ? bval : 0.01f * bval;
            }
            Bs[kr][bv] = bval;
        }
        __syncthreads();

        // ---- compute ----
#pragma unroll
        for (int kk = 0; kk < 16; kk++) {
            float a[8], b[8];
            *(float4*)&a[0] = *(const float4*)&As[kk][mbase];
            *(float4*)&a[4] = *(const float4*)&As[kk][mbase + 4];
            *(float4*)&b[0] = *(const float4*)&Bs[kk][nbase];
            *(float4*)&b[4] = *(const float4*)&Bs[kk][nbase + 4];
#pragma unroll
            for (int i = 0; i < 8; i++)
#pragma unroll
                for (int j = 0; j < 8; j++)
                    acc[i][j] += a[i] * b[j];
        }
        __syncthreads();
    }

    // ---- epilogue: scale by gathered w, vectorized stores ----
    if (n0 + nbase < NVR) {   // thread's 8 v's are all-valid or all-invalid (8000 % 8 == 0)
        int rv[8];
#pragma unroll
        for (int j = 0; j < 8; j++) rv[j] = roi_s[nbase + j];
#pragma unroll
        for (int i = 0; i < 8; i++) {
            int m = m0 + mbase + i;
            int c = m & Cmask;
            int b = m >> Cshift;
            const float* wrow = w + (size_t)c * NVT;
            float ws[8];
#pragma unroll
            for (int j = 0; j < 8; j++) ws[j] = __ldg(wrow + rv[j]);
            float4 o0, o1;
            o0.x = acc[i][0] * ws[0]; o0.y = acc[i][1] * ws[1];
            o0.z = acc[i][2] * ws[2]; o0.w = acc[i][3] * ws[3];
            o1.x = acc[i][4] * ws[4]; o1.y = acc[i][5] * ws[5];
            o1.z = acc[i][6] * ws[6]; o1.w = acc[i][7] * ws[7];
            float* op = out + (size_t)(b * COUT + coff + c) * NVR + n0 + nbase;
            *(float4*)op = o0;
            *(float4*)(op + 4) = o1;
        }
    }
}

extern "C" void kernel_launch(void* const* d_in, const int* in_sizes, int n_in,
                              void* d_out, int out_size)
{
    // Identify inputs by unique element counts (robust to metadata ordering).
    static const int FM[4] = {1605632, 802816, 401408, 200704};     // 8*C*h*h
    static const int RFS[4] = {62720000, 15680000, 3920000, 980000}; // h*h*20000
    static const int WS[4] = {1280000, 2560000, 5120000, 10240000};  // C*20000

    Params p;
    const void* roi = nullptr;
    for (int i = 0; i < n_in; i++) {
        int n = in_sizes[i];
        for (int l = 0; l < 4; l++) {
            if (n == FM[l])  p.fmap[l] = (const float*)d_in[i];
            if (n == RFS[l]) p.rf[l]   = (const float*)d_in[i];
            if (n == WS[l])  p.w[l]    = (const float*)d_in[i];
        }
        if (n == NVR) roi = d_in[i];
    }

    const int Ks[4] = {3136, 784, 196, 49};
    const int Cs[4] = {64, 128, 256, 512};
    const int Csh[4] = {6, 7, 8, 9};
    int off = 0, ms = 0;
    for (int l = 0; l < 4; l++) {
        p.K[l] = Ks[l];
        p.Cmask[l] = Cs[l] - 1;
        p.Cshift[l] = Csh[l];
        p.chan_off[l] = off; off += Cs[l];
        p.mstart[l] = ms;    ms += (BATCH * Cs[l]) / 128;   // 4, 8, 16, 32 -> total 60
    }

    prep_roi_kernel<<<(NVR + 255) / 256, 256>>>(roi);

    dim3 grid(63, 60);   // 63 n-tiles (ceil(8000/128)), 60 m-tiles across all layers
    fused_layer_gemm<<<grid, 256>>>(p, (float*)d_out);
}

// round 3
// speedup vs baseline: 1.0377x; 1.0377x over previous
#include <cuda_runtime.h>
#include <cstdint>

#define NVT 20000      // total voxels
#define NVR 8000       // roi voxels
#define COUT 960       // 64+128+256+512
#define BATCH 8

// Normalized roi indices (int32), filled by prep kernel.
__device__ int g_roi[NVR];

__global__ void prep_roi_kernel(const void* __restrict__ roi_raw) {
    int i = blockIdx.x * blockDim.x + threadIdx.x;
    if (i >= NVR) return;
    const int* p32 = (const int*)roi_raw;
    bool is64 = true;
#pragma unroll
    for (int j = 0; j < 8; j++) is64 = is64 && (p32[2 * j + 1] == 0);
    int v;
    if (is64) v = (int)((const long long*)roi_raw)[i];
    else      v = p32[i];
    g_roi[i] = v;
}

struct Params {
    const float* fmap[4];
    const float* rf[4];
    const float* w[4];
    int K[4];
    int Cmask[4];
    int Cshift[4];
    int chan_off[4];
    int mstart[4];
};

// Packed fp32x2 FMA (Blackwell): d = a * b + d on two lanes.
__device__ __forceinline__ void fma2(unsigned long long& d,
                                     unsigned long long a,
                                     unsigned long long b) {
    asm("fma.rn.f32x2 %0, %1, %2, %0;" : "+l"(d) : "l"(a), "l"(b));
}

// Broadcast one float into both lanes of a b64.
__device__ __forceinline__ unsigned long long bcast2(float x) {
    unsigned long long r;
    asm("mov.b64 %0, {%1, %1};" : "=l"(r) : "f"(x));
    return r;
}

// Fused per-layer SGEMM: out[b, coff+c, v] = (fmap[b,c,:] . lrelu(rf[:,roi[v]])) * w[c,roi[v]]
// Tile: 128(M) x 128(N) x 16(K), 256 threads, 8x8 micro-tile via packed f32x2 FMA.
// Double-buffered smem with register prefetch.
__global__ __launch_bounds__(256, 2)
void fused_layer_gemm(Params prm, float* __restrict__ out)
{
    __shared__ float As[2][16][132];   // padded: conflict-free transpose stores
    __shared__ float Bs[2][16][128];
    __shared__ int   roi_s[128];

    const int nt = blockIdx.x;
    const int my = blockIdx.y;
    const int layer = (my >= 28) ? 3 : (my >= 12) ? 2 : (my >= 4) ? 1 : 0;

    const float* __restrict__ fmap = prm.fmap[layer];
    const float* __restrict__ rf   = prm.rf[layer];
    const float* __restrict__ w    = prm.w[layer];
    const int K      = prm.K[layer];
    const int Cmask  = prm.Cmask[layer];
    const int Cshift = prm.Cshift[layer];
    const int coff   = prm.chan_off[layer];
    const int mtile  = my - prm.mstart[layer];

    const int m0 = mtile * 128;
    const int n0 = nt * 128;
    const int tid = threadIdx.x;

    if (tid < 128) {
        int v = n0 + tid;
        roi_s[tid] = (v < NVR) ? g_roi[v] : 0;
    }
    __syncthreads();

    const int tm = tid >> 4, tn = tid & 15;
    const int mbase = tm * 8, nbase = tn * 8;

    // A-load mapping: 4 threads x 4 floats per 16-float k-row; 64 rows/pass, 2 passes.
    const int ar = tid >> 2;
    const int ak = (tid & 3) << 2;
    // B-load mapping: 128 threads across v, 2 k-rows per pass, 8 passes.
    const int bv = tid & 127;
    const int bk = tid >> 7;
    const int roi_v = roi_s[bv];
    const bool kvec = (K & 3) == 0;   // float4 A loads safe (fails only for K=49)

    const float* arow0 = fmap + (size_t)(m0 + ar) * K;
    const float* arow1 = fmap + (size_t)(m0 + ar + 64) * K;
    const float* rcol  = rf + roi_v;

    // Prefetch registers
    float pa[2][4];
    float pb[8];

    auto load_tile = [&](int k0) {
        // A
#pragma unroll
        for (int h = 0; h < 2; h++) {
            const float* ap = (h ? arow1 : arow0) + k0 + ak;
            float a0 = 0.f, a1 = 0.f, a2 = 0.f, a3 = 0.f;
            int k = k0 + ak;
            if (kvec && k + 4 <= K) {
                float4 t = *(const float4*)ap;
                a0 = t.x; a1 = t.y; a2 = t.z; a3 = t.w;
            } else {
                if (k + 0 < K) a0 = ap[0];
                if (k + 1 < K) a1 = ap[1];
                if (k + 2 < K) a2 = ap[2];
                if (k + 3 < K) a3 = ap[3];
            }
            pa[h][0] = a0; pa[h][1] = a1; pa[h][2] = a2; pa[h][3] = a3;
        }
        // B: gather + leaky_relu
#pragma unroll
        for (int j = 0; j < 8; j++) {
            int k = k0 + bk + 2 * j;
            float bval = 0.f;
            if (k < K) {
                bval = __ldg(rcol + (size_t)k * NVT);
                bval = (bval > 0.f) ? bval : 0.01f * bval;
            }
            pb[j] = bval;
        }
    };

    auto store_tile = [&](int buf) {
#pragma unroll
        for (int h = 0; h < 2; h++) {
            As[buf][ak + 0][ar + h * 64] = pa[h][0];
            As[buf][ak + 1][ar + h * 64] = pa[h][1];
            As[buf][ak + 2][ar + h * 64] = pa[h][2];
            As[buf][ak + 3][ar + h * 64] = pa[h][3];
        }
#pragma unroll
        for (int j = 0; j < 8; j++)
            Bs[buf][bk + 2 * j][bv] = pb[j];
    };

    unsigned long long acc[8][4];
#pragma unroll
    for (int i = 0; i < 8; i++)
#pragma unroll
        for (int j = 0; j < 4; j++) acc[i][j] = 0ull;

    // Prologue: fill buffer 0
    load_tile(0);
    store_tile(0);
    __syncthreads();

    int buf = 0;
    for (int k0 = 0; k0 < K; k0 += 16) {
        const bool has_next = (k0 + 16) < K;
        if (has_next) load_tile(k0 + 16);

        // ---- compute on smem[buf] ----
#pragma unroll
        for (int kk = 0; kk < 16; kk++) {
            float a[8];
            unsigned long long b[4];
            *(float4*)&a[0] = *(const float4*)&As[buf][kk][mbase];
            *(float4*)&a[4] = *(const float4*)&As[buf][kk][mbase + 4];
            {
                ulonglong2 t0 = *(const ulonglong2*)&Bs[buf][kk][nbase];
                ulonglong2 t1 = *(const ulonglong2*)&Bs[buf][kk][nbase + 4];
                b[0] = t0.x; b[1] = t0.y; b[2] = t1.x; b[3] = t1.y;
            }
#pragma unroll
            for (int i = 0; i < 8; i++) {
                unsigned long long ap = bcast2(a[i]);
                fma2(acc[i][0], ap, b[0]);
                fma2(acc[i][1], ap, b[1]);
                fma2(acc[i][2], ap, b[2]);
                fma2(acc[i][3], ap, b[3]);
            }
        }

        if (has_next) store_tile(buf ^ 1);
        __syncthreads();
        buf ^= 1;
    }

    // ---- epilogue: scale by gathered w, vectorized stores ----
    if (n0 + nbase < NVR) {   // 8000 % 8 == 0: all-valid or all-invalid per thread
        int rv[8];
#pragma unroll
        for (int j = 0; j < 8; j++) rv[j] = roi_s[nbase + j];
#pragma unroll
        for (int i = 0; i < 8; i++) {
            int m = m0 + mbase + i;
            int c = m & Cmask;
            int b = m >> Cshift;
            const float* wrow = w + (size_t)c * NVT;
            float ws[8];
#pragma unroll
            for (int j = 0; j < 8; j++) ws[j] = __ldg(wrow + rv[j]);
            float2 p0 = *reinterpret_cast<float2*>(&acc[i][0]);
            float2 p1 = *reinterpret_cast<float2*>(&acc[i][1]);
            float2 p2 = *reinterpret_cast<float2*>(&acc[i][2]);
            float2 p3 = *reinterpret_cast<float2*>(&acc[i][3]);
            float4 o0, o1;
            o0.x = p0.x * ws[0]; o0.y = p0.y * ws[1];
            o0.z = p1.x * ws[2]; o0.w = p1.y * ws[3];
            o1.x = p2.x * ws[4]; o1.y = p2.y * ws[5];
            o1.z = p3.x * ws[6]; o1.w = p3.y * ws[7];
            float* op = out + (size_t)(b * COUT + coff + c) * NVR + n0 + nbase;
            *(float4*)op = o0;
            *(float4*)(op + 4) = o1;
        }
    }
}

extern "C" void kernel_launch(void* const* d_in, const int* in_sizes, int n_in,
                              void* d_out, int out_size)
{
    // Identify inputs by unique element counts (robust to metadata ordering).
    static const int FM[4] = {1605632, 802816, 401408, 200704};     // 8*C*h*h
    static const int RFS[4] = {62720000, 15680000, 3920000, 980000}; // h*h*20000
    static const int WS[4] = {1280000, 2560000, 5120000, 10240000};  // C*20000

    Params p;
    const void* roi = nullptr;
    for (int i = 0; i < n_in; i++) {
        int n = in_sizes[i];
        for (int l = 0; l < 4; l++) {
            if (n == FM[l])  p.fmap[l] = (const float*)d_in[i];
            if (n == RFS[l]) p.rf[l]   = (const float*)d_in[i];
            if (n == WS[l])  p.w[l]    = (const float*)d_in[i];
        }
        if (n == NVR) roi = d_in[i];
    }

    const int Ks[4] = {3136, 784, 196, 49};
    const int Cs[4] = {64, 128, 256, 512};
    const int Csh[4] = {6, 7, 8, 9};
    int off = 0, ms = 0;
    for (int l = 0; l < 4; l++) {
        p.K[l] = Ks[l];
        p.Cmask[l] = Cs[l] - 1;
        p.Cshift[l] = Csh[l];
        p.chan_off[l] = off; off += Cs[l];
        p.mstart[l] = ms;    ms += (BATCH * Cs[l]) / 128;   // 4, 8, 16, 32 -> total 60
    }

    prep_roi_kernel<<<(NVR + 255) / 256, 256>>>(roi);

    dim3 grid(63, 60);   // 63 n-tiles (ceil(8000/128)), 60 m-tiles across all layers
    fused_layer_gemm<<<grid, 256>>>(p, (float*)d_out);
}

// round 10
// speedup vs baseline: 1.1339x; 1.0928x over previous
#include <cuda_runtime.h>
#include <cuda_bf16.h>
#include <cstdint>

#define NVT 20000
#define NVR 8000
#define COUT 960

// ---------------- static device scratch ----------------
__device__ int g_roi[NVR];
// Gathered+activated rf, transposed to [v][k], K padded per layer, bf16 hi/lo.
// Sum over layers of 8064 * Kpad = 8064*(3136+832+256+64) = 34,578,432 elems.
__device__ __align__(128) __nv_bfloat16 g_Gh[34578432];
__device__ __align__(128) __nv_bfloat16 g_Gl[34578432];
// fmap split: sum M*Kpad = 512*3136+1024*832+2048*256+4096*64 = 3,244,032
__device__ __align__(128) __nv_bfloat16 g_Fh[3244032];
__device__ __align__(128) __nv_bfloat16 g_Fl[3244032];
// gathered w: [960][8000]
__device__ __align__(16) float g_wp[COUT * NVR];

struct Params {
    const float* fmap[4];
    const float* rf[4];
    const float* w[4];
    int K[4];
    int Kpad[4];
    int nch[4];
    int Cmask[4];
    int Csh[4];
    int coff[4];
    int mstart[4];
    size_t Goff[4];
    size_t Foff[4];
};

// ---------------- PTX helpers (base sm_103 target, no 'a' features) ----------
__device__ __forceinline__ uint32_t smem_u32(const void* p) {
    uint32_t a;
    asm("{ .reg .u64 t; cvta.to.shared.u64 t, %1; cvt.u32.u64 %0, t; }" : "=r"(a) : "l"(p));
    return a;
}
__device__ __forceinline__ void cpa16(uint32_t s, const void* g) {
    asm volatile("cp.async.cg.shared.global [%0], [%1], 16;" :: "r"(s), "l"(g));
}
__device__ __forceinline__ void ldsm_x4(uint32_t* r, uint32_t addr) {
    asm volatile("ldmatrix.sync.aligned.m8n8.x4.shared.b16 {%0,%1,%2,%3}, [%4];"
                 : "=r"(r[0]), "=r"(r[1]), "=r"(r[2]), "=r"(r[3]) : "r"(addr));
}
__device__ __forceinline__ void mma16816(float* d, const uint32_t* a, uint32_t b0, uint32_t b1) {
    asm volatile("mma.sync.aligned.m16n8k16.row.col.f32.bf16.bf16.f32 "
                 "{%0,%1,%2,%3}, {%4,%5,%6,%7}, {%8,%9}, {%0,%1,%2,%3};"
                 : "+f"(d[0]), "+f"(d[1]), "+f"(d[2]), "+f"(d[3])
                 : "r"(a[0]), "r"(a[1]), "r"(a[2]), "r"(a[3]), "r"(b0), "r"(b1));
}
// XOR swizzle: row r, byte-col kb (0..127): conflict-free STS + LDSM.
__device__ __forceinline__ uint32_t tile_addr(uint32_t base, int r, int kb) {
    return base + r * 128 + (kb ^ ((r & 7) << 4));
}

// ---------------- prep: normalize roi to int32 ----------------
__global__ void prep_roi_kernel(const void* __restrict__ roi_raw) {
    int i = blockIdx.x * blockDim.x + threadIdx.x;
    if (i >= NVR) return;
    const int* p32 = (const int*)roi_raw;
    bool is64 = true;
#pragma unroll
    for (int j = 0; j < 8; j++) is64 = is64 && (p32[2 * j + 1] == 0);
    g_roi[i] = is64 ? (int)((const long long*)roi_raw)[i] : p32[i];
}

// ---------------- pack w: g_wp[co][v] = w_l[c][roi[v]] ----------------
__global__ void pack_w_kernel(Params p) {
    int idx = blockIdx.x * 256 + threadIdx.x;
    int co = idx / NVR;
    int v = idx - co * NVR;
    int layer = (co >= 448) ? 3 : (co >= 192) ? 2 : (co >= 64) ? 1 : 0;
    int c = co - p.coff[layer];
    g_wp[idx] = p.w[layer][(size_t)c * NVT + g_roi[v]];
}

// ---------------- pack F: bf16 hi/lo split of fmap, K padded ----------------
__global__ void pack_F_kernel(Params p) {
    int e = blockIdx.x * 256 + threadIdx.x;
    int layer = (e >= 2981888) ? 3 : (e >= 2457600) ? 2 : (e >= 1605632) ? 1 : 0;
    int local = e - (int)p.Foff[layer];
    int Kp = p.Kpad[layer], K = p.K[layer];
    int m = local / Kp;
    int k = local - m * Kp;
    float v = (k < K) ? p.fmap[layer][(size_t)m * K + k] : 0.f;
    __nv_bfloat16 h = __float2bfloat16(v);
    __nv_bfloat16 l = __float2bfloat16(v - __bfloat162float(h));
    g_Fh[e] = h;
    g_Fl[e] = l;
}

// ---------------- pack G: gather + lrelu + transpose + bf16 hi/lo ----------------
__global__ void pack_G_kernel(Params p) {
    __shared__ float s[64][132];
    __shared__ int roi_s[128];
    int bx = blockIdx.x;
    int layer = (bx >= 66) ? 3 : (bx >= 62) ? 2 : (bx >= 49) ? 1 : 0;
    const int ktst0 = (layer == 0) ? 0 : (layer == 1) ? 49 : (layer == 2) ? 62 : 66;
    int k0 = (bx - ktst0) * 64;
    int v0 = blockIdx.y * 128;
    int tid = threadIdx.x;
    if (tid < 128) roi_s[tid] = (v0 + tid < NVR) ? g_roi[v0 + tid] : 0;
    __syncthreads();
    int K = p.K[layer], Kp = p.Kpad[layer];
    const float* __restrict__ rf = p.rf[layer];
    int vl = tid & 127, kh = tid >> 7;
    int rv = roi_s[vl];
#pragma unroll
    for (int j = 0; j < 32; j++) {
        int kl = kh * 32 + j;
        int k = k0 + kl;
        float val = 0.f;
        if (k < K) {
            val = __ldg(rf + (size_t)k * NVT + rv);
            val = (val > 0.f) ? val : 0.01f * val;
        }
        s[kl][vl] = val;
    }
    __syncthreads();
    int vl2 = tid >> 1, kq = tid & 1;
    uint32_t hw[16], lw[16];
#pragma unroll
    for (int jj = 0; jj < 16; jj++) {
        float x0 = s[kq * 32 + 2 * jj][vl2];
        float x1 = s[kq * 32 + 2 * jj + 1][vl2];
        __nv_bfloat16 h0 = __float2bfloat16(x0);
        __nv_bfloat16 h1 = __float2bfloat16(x1);
        __nv_bfloat16 l0 = __float2bfloat16(x0 - __bfloat162float(h0));
        __nv_bfloat16 l1 = __float2bfloat16(x1 - __bfloat162float(h1));
        hw[jj] = (uint32_t)__bfloat16_as_ushort(h0) | ((uint32_t)__bfloat16_as_ushort(h1) << 16);
        lw[jj] = (uint32_t)__bfloat16_as_ushort(l0) | ((uint32_t)__bfloat16_as_ushort(l1) << 16);
    }
    size_t base = p.Goff[layer] + (size_t)(v0 + vl2) * Kp + k0 + kq * 32;
    uint4* dh = reinterpret_cast<uint4*>(g_Gh + base);
    uint4* dl = reinterpret_cast<uint4*>(g_Gl + base);
#pragma unroll
    for (int q = 0; q < 4; q++) {
        dh[q] = make_uint4(hw[4 * q], hw[4 * q + 1], hw[4 * q + 2], hw[4 * q + 3]);
        dl[q] = make_uint4(lw[4 * q], lw[4 * q + 1], lw[4 * q + 2], lw[4 * q + 3]);
    }
}

// ---------------- mma.sync GEMM (HMMA fallback path) ----------------
// CTA tile: 128 channels (M) x 128 voxels (N) x 64 (K-chunk), 8 warps (4m x 2n),
// warp tile 32x64. 3-term bf16 hi/lo split. Double-buffered cp.async smem.
// smem per buf: Ah|Al|Bh|Bl, 16KB each = 64KB; x2 = 128KB dynamic.
#define GEMM_SMEM 131072

__global__ __launch_bounds__(256, 1) void gemm_mma(Params p, float* __restrict__ out) {
    extern __shared__ __align__(128) char smem[];
    const uint32_t sb = smem_u32(smem);
    const int tid = threadIdx.x;
    const int wid = tid >> 5, lid = tid & 31;
    const int warp_m = wid & 3, warp_n = wid >> 2;

    const int vt = blockIdx.x;
    const int my = blockIdx.y;
    const int layer = (my >= 28) ? 3 : (my >= 12) ? 2 : (my >= 4) ? 1 : 0;
    const int m0 = (my - p.mstart[layer]) * 128;   // layer-local channel-row base
    const int v0 = vt * 128;
    const size_t goff = p.Goff[layer];
    const size_t foff = p.Foff[layer];
    const int Kp = p.Kpad[layer];
    const int nch = p.nch[layer];

    // ---- async tile loader ----
    auto load_chunk = [&](int buf, int k0) {
        uint32_t sbase = sb + buf * 65536;
#pragma unroll
        for (int i = 0; i < 16; i++) {
            int flat = (i << 8) + tid;
            int arr = flat >> 10;            // 0:Fh 1:Fl 2:Gh 3:Gl (compile-time per i)
            int r = (flat >> 3) & 127;
            int q = flat & 7;
            const __nv_bfloat16* src;
            if (arr == 0)      src = g_Fh + foff + (size_t)(m0 + r) * Kp + k0 + q * 8;
            else if (arr == 1) src = g_Fl + foff + (size_t)(m0 + r) * Kp + k0 + q * 8;
            else if (arr == 2) src = g_Gh + goff + (size_t)(v0 + r) * Kp + k0 + q * 8;
            else               src = g_Gl + goff + (size_t)(v0 + r) * Kp + k0 + q * 8;
            cpa16(sbase + arr * 16384 + r * 128 + ((q * 16) ^ ((r & 7) << 4)), src);
        }
        asm volatile("cp.async.commit_group;" ::: "memory");
    };

    float d[2][8][4];
#pragma unroll
    for (int i = 0; i < 2; i++)
#pragma unroll
        for (int j = 0; j < 8; j++)
#pragma unroll
            for (int q = 0; q < 4; q++) d[i][j][q] = 0.f;

    // ldmatrix lane addressing: mat = lid>>3; within-mat row = lid&7
    const int frow = ((lid >> 3) & 1) * 8 + (lid & 7);   // +0/+8 row select
    const int fkb = (lid >> 4) * 16;                     // +0/+16 byte-col select

    load_chunk(0, 0);

    int buf = 0;
    for (int c = 0; c < nch; c++) {
        if (c + 1 < nch) {
            load_chunk(buf ^ 1, (c + 1) * 64);
            asm volatile("cp.async.wait_group 1;" ::: "memory");
        } else {
            asm volatile("cp.async.wait_group 0;" ::: "memory");
        }
        __syncthreads();

        const uint32_t Ah = sb + buf * 65536;
        const uint32_t Al = Ah + 16384;
        const uint32_t Bh = Ah + 32768;
        const uint32_t Bl = Ah + 49152;

#pragma unroll
        for (int ks = 0; ks < 4; ks++) {
            const int kb = ks * 32 + fkb;
            uint32_t ah[2][4], al[2][4], bh[4][4], bl[4][4];
#pragma unroll
            for (int mf = 0; mf < 2; mf++) {
                int r = warp_m * 32 + mf * 16 + frow;
                ldsm_x4(ah[mf], tile_addr(Ah, r, kb));
                ldsm_x4(al[mf], tile_addr(Al, r, kb));
            }
#pragma unroll
            for (int pr = 0; pr < 4; pr++) {
                int r = warp_n * 64 + pr * 16 + frow;
                ldsm_x4(bh[pr], tile_addr(Bh, r, kb));
                ldsm_x4(bl[pr], tile_addr(Bl, r, kb));
            }
#pragma unroll
            for (int mf = 0; mf < 2; mf++)
#pragma unroll
                for (int nf = 0; nf < 8; nf++) {
                    const int pr = nf >> 1, s = nf & 1;
                    mma16816(d[mf][nf], ah[mf], bh[pr][s], bh[pr][2 + s]);
                    mma16816(d[mf][nf], al[mf], bh[pr][s], bh[pr][2 + s]);
                    mma16816(d[mf][nf], ah[mf], bl[pr][s], bl[pr][2 + s]);
                }
        }
        __syncthreads();
        buf ^= 1;
    }

    // ---- epilogue: scale by g_wp, float2 stores ----
    const int Cm = p.Cmask[layer], Cs = p.Csh[layer], co0 = p.coff[layer];
    const int vbase = v0 + warp_n * 64 + (lid & 3) * 2;
#pragma unroll
    for (int mf = 0; mf < 2; mf++) {
        const int mrow = m0 + warp_m * 32 + mf * 16 + (lid >> 2);
#pragma unroll
        for (int half = 0; half < 2; half++) {
            const int m = mrow + half * 8;
            const int cch = m & Cm;
            const int b = m >> Cs;
            const int co = co0 + cch;
            const float* wrow = g_wp + (size_t)co * NVR;
            float* orow = out + ((size_t)(b * COUT + co)) * NVR;
#pragma unroll
            for (int nf = 0; nf < 8; nf++) {
                const int v = vbase + nf * 8;
                if (v < NVR) {
                    float2 wp = *reinterpret_cast<const float2*>(wrow + v);
                    float2 o;
                    o.x = d[mf][nf][half * 2 + 0] * wp.x;
                    o.y = d[mf][nf][half * 2 + 1] * wp.y;
                    *reinterpret_cast<float2*>(orow + v) = o;
                }
            }
        }
    }
}

// ---------------- host ----------------
extern "C" void kernel_launch(void* const* d_in, const int* in_sizes, int n_in,
                              void* d_out, int out_size)
{
    static const int FM[4] = {1605632, 802816, 401408, 200704};
    static const int RFS[4] = {62720000, 15680000, 3920000, 980000};
    static const int WS[4] = {1280000, 2560000, 5120000, 10240000};

    Params p;
    const void* roi = nullptr;
    for (int i = 0; i < n_in; i++) {
        int n = in_sizes[i];
        for (int l = 0; l < 4; l++) {
            if (n == FM[l])  p.fmap[l] = (const float*)d_in[i];
            if (n == RFS[l]) p.rf[l]   = (const float*)d_in[i];
            if (n == WS[l])  p.w[l]    = (const float*)d_in[i];
        }
        if (n == NVR) roi = d_in[i];
    }

    const int Ks[4]   = {3136, 784, 196, 49};
    const int Kps[4]  = {3136, 832, 256, 64};
    const int Cs[4]   = {64, 128, 256, 512};
    const int Csh[4]  = {6, 7, 8, 9};
    size_t go = 0, fo = 0;
    int coff = 0, ms = 0;
    for (int l = 0; l < 4; l++) {
        p.K[l] = Ks[l];
        p.Kpad[l] = Kps[l];
        p.nch[l] = Kps[l] / 64;
        p.Cmask[l] = Cs[l] - 1;
        p.Csh[l] = Csh[l];
        p.coff[l] = coff; coff += Cs[l];
        p.mstart[l] = ms; ms += (8 * Cs[l]) / 128;   // 4, 8, 16, 32 -> 60 m-tiles
        p.Goff[l] = go;  go += (size_t)8064 * Kps[l];
        p.Foff[l] = fo;  fo += (size_t)(8 * Cs[l]) * Kps[l];
    }

    prep_roi_kernel<<<32, 256>>>(roi);
    pack_w_kernel<<<COUT * NVR / 256, 256>>>(p);
    pack_F_kernel<<<3244032 / 256, 256>>>(p);
    pack_G_kernel<<<dim3(67, 63), 256>>>(p);

    cudaFuncSetAttribute(gemm_mma, cudaFuncAttributeMaxDynamicSharedMemorySize, GEMM_SMEM);
    gemm_mma<<<dim3(63, 60), 256, GEMM_SMEM>>>(p, (float*)d_out);
}

// round 11
// speedup vs baseline: 1.5633x; 1.3787x over previous
#include <cuda_runtime.h>
#include <cuda_bf16.h>
#include <cstdint>

#define NVT 20000
#define NVR 8000
#define COUT 960

// ---------------- static device scratch ----------------
__device__ int g_roi[NVR];
// Gathered+activated rf, transposed to [v][k], K padded per layer, bf16 hi/lo.
__device__ __align__(128) __nv_bfloat16 g_Gh[34578432];
__device__ __align__(128) __nv_bfloat16 g_Gl[34578432];
// fmap split: sum M*Kpad = 3,244,032
__device__ __align__(128) __nv_bfloat16 g_Fh[3244032];
__device__ __align__(128) __nv_bfloat16 g_Fl[3244032];
// gathered w: [960][8000]
__device__ __align__(16) float g_wp[COUT * NVR];

struct Params {
    const float* fmap[4];
    const float* rf[4];
    const float* w[4];
    int K[4];
    int Kpad[4];
    int nch[4];
    int Cmask[4];
    int Csh[4];
    int coff[4];
    int mstart[4];
    size_t Goff[4];
    size_t Foff[4];
};

// ---------------- PTX helpers (base sm_103 target, no 'a' features) ----------
__device__ __forceinline__ uint32_t smem_u32(const void* p) {
    uint32_t a;
    asm("{ .reg .u64 t; cvta.to.shared.u64 t, %1; cvt.u32.u64 %0, t; }" : "=r"(a) : "l"(p));
    return a;
}
__device__ __forceinline__ void cpa16(uint32_t s, const void* g) {
    asm volatile("cp.async.cg.shared.global [%0], [%1], 16;" :: "r"(s), "l"(g));
}
__device__ __forceinline__ void ldsm_x4(uint32_t* r, uint32_t addr) {
    asm volatile("ldmatrix.sync.aligned.m8n8.x4.shared.b16 {%0,%1,%2,%3}, [%4];"
                 : "=r"(r[0]), "=r"(r[1]), "=r"(r[2]), "=r"(r[3]) : "r"(addr));
}
__device__ __forceinline__ void mma16816(float* d, const uint32_t* a, uint32_t b0, uint32_t b1) {
    asm volatile("mma.sync.aligned.m16n8k16.row.col.f32.bf16.bf16.f32 "
                 "{%0,%1,%2,%3}, {%4,%5,%6,%7}, {%8,%9}, {%0,%1,%2,%3};"
                 : "+f"(d[0]), "+f"(d[1]), "+f"(d[2]), "+f"(d[3])
                 : "r"(a[0]), "r"(a[1]), "r"(a[2]), "r"(a[3]), "r"(b0), "r"(b1));
}
// 64B-row tile swizzle: row r, byte-col kb in {0,16,32,48}.
// addr = r*64 + (kb ^ ((r<<3)&48)); 8-row LDSM wavefronts hit 8 distinct 16B banks.
__device__ __forceinline__ uint32_t taddr64(uint32_t base, int r, int kb) {
    return base + r * 64 + (kb ^ ((r << 3) & 48));
}

// ---------------- prep: normalize roi to int32 ----------------
__global__ void prep_roi_kernel(const void* __restrict__ roi_raw) {
    int i = blockIdx.x * blockDim.x + threadIdx.x;
    if (i >= NVR) return;
    const int* p32 = (const int*)roi_raw;
    bool is64 = true;
#pragma unroll
    for (int j = 0; j < 8; j++) is64 = is64 && (p32[2 * j + 1] == 0);
    g_roi[i] = is64 ? (int)((const long long*)roi_raw)[i] : p32[i];
}

// ---------------- pack w: g_wp[co][v] = w_l[c][roi[v]] ----------------
__global__ void pack_w_kernel(Params p) {
    int idx = blockIdx.x * 256 + threadIdx.x;
    int co = idx / NVR;
    int v = idx - co * NVR;
    int layer = (co >= 448) ? 3 : (co >= 192) ? 2 : (co >= 64) ? 1 : 0;
    int c = co - p.coff[layer];
    g_wp[idx] = p.w[layer][(size_t)c * NVT + g_roi[v]];
}

// ---------------- pack F: bf16 hi/lo split of fmap, K padded ----------------
__global__ void pack_F_kernel(Params p) {
    int e = blockIdx.x * 256 + threadIdx.x;
    int layer = (e >= 2981888) ? 3 : (e >= 2457600) ? 2 : (e >= 1605632) ? 1 : 0;
    int local = e - (int)p.Foff[layer];
    int Kp = p.Kpad[layer], K = p.K[layer];
    int m = local / Kp;
    int k = local - m * Kp;
    float v = (k < K) ? p.fmap[layer][(size_t)m * K + k] : 0.f;
    __nv_bfloat16 h = __float2bfloat16(v);
    __nv_bfloat16 l = __float2bfloat16(v - __bfloat162float(h));
    g_Fh[e] = h;
    g_Fl[e] = l;
}

// ---------------- pack G: gather + lrelu + transpose + bf16 hi/lo ----------------
__global__ void pack_G_kernel(Params p) {
    __shared__ float s[64][132];
    __shared__ int roi_s[128];
    int bx = blockIdx.x;
    int layer = (bx >= 66) ? 3 : (bx >= 62) ? 2 : (bx >= 49) ? 1 : 0;
    const int ktst0 = (layer == 0) ? 0 : (layer == 1) ? 49 : (layer == 2) ? 62 : 66;
    int k0 = (bx - ktst0) * 64;
    int v0 = blockIdx.y * 128;
    int tid = threadIdx.x;
    if (tid < 128) roi_s[tid] = (v0 + tid < NVR) ? g_roi[v0 + tid] : 0;
    __syncthreads();
    int K = p.K[layer], Kp = p.Kpad[layer];
    const float* __restrict__ rf = p.rf[layer];
    int vl = tid & 127, kh = tid >> 7;
    int rv = roi_s[vl];
#pragma unroll
    for (int j = 0; j < 32; j++) {
        int kl = kh * 32 + j;
        int k = k0 + kl;
        float val = 0.f;
        if (k < K) {
            val = __ldg(rf + (size_t)k * NVT + rv);
            val = (val > 0.f) ? val : 0.01f * val;
        }
        s[kl][vl] = val;
    }
    __syncthreads();
    int vl2 = tid >> 1, kq = tid & 1;
    uint32_t hw[16], lw[16];
#pragma unroll
    for (int jj = 0; jj < 16; jj++) {
        float x0 = s[kq * 32 + 2 * jj][vl2];
        float x1 = s[kq * 32 + 2 * jj + 1][vl2];
        __nv_bfloat16 h0 = __float2bfloat16(x0);
        __nv_bfloat16 h1 = __float2bfloat16(x1);
        __nv_bfloat16 l0 = __float2bfloat16(x0 - __bfloat162float(h0));
        __nv_bfloat16 l1 = __float2bfloat16(x1 - __bfloat162float(h1));
        hw[jj] = (uint32_t)__bfloat16_as_ushort(h0) | ((uint32_t)__bfloat16_as_ushort(h1) << 16);
        lw[jj] = (uint32_t)__bfloat16_as_ushort(l0) | ((uint32_t)__bfloat16_as_ushort(l1) << 16);
    }
    size_t base = p.Goff[layer] + (size_t)(v0 + vl2) * Kp + k0 + kq * 32;
    uint4* dh = reinterpret_cast<uint4*>(g_Gh + base);
    uint4* dl = reinterpret_cast<uint4*>(g_Gl + base);
#pragma unroll
    for (int q = 0; q < 4; q++) {
        dh[q] = make_uint4(hw[4 * q], hw[4 * q + 1], hw[4 * q + 2], hw[4 * q + 3]);
        dl[q] = make_uint4(lw[4 * q], lw[4 * q + 1], lw[4 * q + 2], lw[4 * q + 3]);
    }
}

// ---------------- mma.sync GEMM ----------------
// CTA tile: 128 ch (M) x 128 vox (N) x 32 (K-chunk), 8 warps (4m x 2n), warp
// tile 32x64, 3-term bf16 hi/lo. 3-stage cp.async pipeline, 2 CTAs/SM.
// smem: 3 stages x (Fh|Fl|Gh|Gl, 8KB each) = 96KB.
#define GEMM_SMEM 98304

__global__ __launch_bounds__(256, 2) void gemm_mma(Params p, float* __restrict__ out) {
    extern __shared__ __align__(128) char smem[];
    const uint32_t sb = smem_u32(smem);
    const int tid = threadIdx.x;
    const int wid = tid >> 5, lid = tid & 31;
    const int warp_m = wid & 3, warp_n = wid >> 2;

    const int my = blockIdx.x;                     // m-tile fastest: L2-friendly
    const int vt = blockIdx.y;
    const int layer = (my >= 28) ? 3 : (my >= 12) ? 2 : (my >= 4) ? 1 : 0;
    const int m0 = (my - p.mstart[layer]) * 128;
    const int v0 = vt * 128;
    const size_t goff = p.Goff[layer];
    const size_t foff = p.Foff[layer];
    const int Kp = p.Kpad[layer];
    const int nch = p.nch[layer];                  // Kpad/32

    const __nv_bfloat16* __restrict__ aF = g_Fh + foff + (size_t)m0 * Kp;
    const __nv_bfloat16* __restrict__ aFl = g_Fl + foff + (size_t)m0 * Kp;
    const __nv_bfloat16* __restrict__ aG = g_Gh + goff + (size_t)v0 * Kp;
    const __nv_bfloat16* __restrict__ aGl = g_Gl + goff + (size_t)v0 * Kp;

    // 8 x 16B per thread per stage: arr(0:Fh 1:Fl 2:Gh 3:Gl), row, quad
    auto load_chunk = [&](int stage, int k0) {
        uint32_t sbase = sb + stage * 32768;
#pragma unroll
        for (int i = 0; i < 8; i++) {
            int flat = (i << 8) + tid;
            int arr = flat >> 9;
            int r = (flat >> 2) & 127;
            int q = flat & 3;
            const __nv_bfloat16* src;
            if (arr == 0)      src = aF  + (size_t)r * Kp + k0 + q * 8;
            else if (arr == 1) src = aFl + (size_t)r * Kp + k0 + q * 8;
            else if (arr == 2) src = aG  + (size_t)r * Kp + k0 + q * 8;
            else               src = aGl + (size_t)r * Kp + k0 + q * 8;
            cpa16(sbase + arr * 8192 + r * 64 + ((q * 16) ^ ((r << 3) & 48)), src);
        }
        asm volatile("cp.async.commit_group;" ::: "memory");
    };

    float d[2][8][4];
#pragma unroll
    for (int i = 0; i < 2; i++)
#pragma unroll
        for (int j = 0; j < 8; j++)
#pragma unroll
            for (int q = 0; q < 4; q++) d[i][j][q] = 0.f;

    const int frow = ((lid >> 3) & 1) * 8 + (lid & 7);
    const int fkb = (lid >> 4) * 16;

    load_chunk(0, 0);
    if (nch > 1) load_chunk(1, 32);

    int stage = 0;
    for (int c = 0; c < nch; c++) {
        if (c + 1 < nch) asm volatile("cp.async.wait_group 1;" ::: "memory");
        else             asm volatile("cp.async.wait_group 0;" ::: "memory");
        __syncthreads();
        if (c + 2 < nch) {
            int s2 = stage + 2; if (s2 >= 3) s2 -= 3;
            load_chunk(s2, (c + 2) * 32);
        }

        const uint32_t Fh = sb + stage * 32768;
        const uint32_t Fl = Fh + 8192;
        const uint32_t Gh = Fh + 16384;
        const uint32_t Gl = Fh + 24576;

#pragma unroll
        for (int ks = 0; ks < 2; ks++) {
            const int kb = ks * 32 + fkb;
            uint32_t ah[2][4], al[2][4], bh[4][4], bl[4][4];
#pragma unroll
            for (int mf = 0; mf < 2; mf++) {
                int r = warp_m * 32 + mf * 16 + frow;
                ldsm_x4(ah[mf], taddr64(Fh, r, kb));
                ldsm_x4(al[mf], taddr64(Fl, r, kb));
            }
#pragma unroll
            for (int pr = 0; pr < 4; pr++) {
                int r = warp_n * 64 + pr * 16 + frow;
                ldsm_x4(bh[pr], taddr64(Gh, r, kb));
                ldsm_x4(bl[pr], taddr64(Gl, r, kb));
            }
#pragma unroll
            for (int mf = 0; mf < 2; mf++)
#pragma unroll
                for (int nf = 0; nf < 8; nf++) {
                    const int pr = nf >> 1, s = nf & 1;
                    mma16816(d[mf][nf], ah[mf], bh[pr][s], bh[pr][2 + s]);
                    mma16816(d[mf][nf], al[mf], bh[pr][s], bh[pr][2 + s]);
                    mma16816(d[mf][nf], ah[mf], bl[pr][s], bl[pr][2 + s]);
                }
        }
        stage++; if (stage >= 3) stage = 0;
    }

    // ---- epilogue: scale by g_wp, float2 stores ----
    const int Cm = p.Cmask[layer], Cs = p.Csh[layer], co0 = p.coff[layer];
    const int vbase = v0 + warp_n * 64 + (lid & 3) * 2;
#pragma unroll
    for (int mf = 0; mf < 2; mf++) {
        const int mrow = m0 + warp_m * 32 + mf * 16 + (lid >> 2);
#pragma unroll
        for (int half = 0; half < 2; half++) {
            const int m = mrow + half * 8;
            const int cch = m & Cm;
            const int b = m >> Cs;
            const int co = co0 + cch;
            const float* wrow = g_wp + (size_t)co * NVR;
            float* orow = out + ((size_t)(b * COUT + co)) * NVR;
#pragma unroll
            for (int nf = 0; nf < 8; nf++) {
                const int v = vbase + nf * 8;
                if (v < NVR) {
                    float2 wp = *reinterpret_cast<const float2*>(wrow + v);
                    float2 o;
                    o.x = d[mf][nf][half * 2 + 0] * wp.x;
                    o.y = d[mf][nf][half * 2 + 1] * wp.y;
                    *reinterpret_cast<float2*>(orow + v) = o;
                }
            }
        }
    }
}

// ---------------- host ----------------
extern "C" void kernel_launch(void* const* d_in, const int* in_sizes, int n_in,
                              void* d_out, int out_size)
{
    static const int FM[4] = {1605632, 802816, 401408, 200704};
    static const int RFS[4] = {62720000, 15680000, 3920000, 980000};
    static const int WS[4] = {1280000, 2560000, 5120000, 10240000};

    Params p;
    const void* roi = nullptr;
    for (int i = 0; i < n_in; i++) {
        int n = in_sizes[i];
        for (int l = 0; l < 4; l++) {
            if (n == FM[l])  p.fmap[l] = (const float*)d_in[i];
            if (n == RFS[l]) p.rf[l]   = (const float*)d_in[i];
            if (n == WS[l])  p.w[l]    = (const float*)d_in[i];
        }
        if (n == NVR) roi = d_in[i];
    }

    const int Ks[4]   = {3136, 784, 196, 49};
    const int Kps[4]  = {3136, 832, 256, 64};
    const int Cs[4]   = {64, 128, 256, 512};
    const int Csh[4]  = {6, 7, 8, 9};
    size_t go = 0, fo = 0;
    int coff = 0, ms = 0;
    for (int l = 0; l < 4; l++) {
        p.K[l] = Ks[l];
        p.Kpad[l] = Kps[l];
        p.nch[l] = Kps[l] / 32;
        p.Cmask[l] = Cs[l] - 1;
        p.Csh[l] = Csh[l];
        p.coff[l] = coff; coff += Cs[l];
        p.mstart[l] = ms; ms += (8 * Cs[l]) / 128;   // 4, 8, 16, 32 -> 60 m-tiles
        p.Goff[l] = go;  go += (size_t)8064 * Kps[l];
        p.Foff[l] = fo;  fo += (size_t)(8 * Cs[l]) * Kps[l];
    }

    prep_roi_kernel<<<32, 256>>>(roi);
    pack_w_kernel<<<COUT * NVR / 256, 256>>>(p);
    pack_F_kernel<<<3244032 / 256, 256>>>(p);
    pack_G_kernel<<<dim3(67, 63), 256>>>(p);

    cudaFuncSetAttribute(gemm_mma, cudaFuncAttributeMaxDynamicSharedMemorySize, GEMM_SMEM);
    gemm_mma<<<dim3(60, 63), 256, GEMM_SMEM>>>(p, (float*)d_out);
}

// round 14
// speedup vs baseline: 1.9742x; 1.2628x over previous
#include <cuda_runtime.h>
#include <cuda_fp16.h>
#include <cstdint>

#define NVT 20000
#define NVR 8000
#define COUT 960

// ---------------- static device scratch ----------------
__device__ int g_roi[NVR];
// Gathered+activated rf, transposed to [v][k], K padded, fp16 (UNSPLIT).
__device__ __align__(128) __half g_G[34578432];
// fmap hi/lo fp16 split: sum M*Kpad = 3,244,032
__device__ __align__(128) __half g_Fh[3244032];
__device__ __align__(128) __half g_Fl[3244032];
// gathered w: [960][8000]
__device__ __align__(16) float g_wp[COUT * NVR];

struct Params {
    const float* fmap[4];
    const float* rf[4];
    const float* w[4];
    int K[4];
    int Kpad[4];
    int nch[4];
    int Cmask[4];
    int Csh[4];
    int coff[4];
    int mstart[4];
    size_t Goff[4];
    size_t Foff[4];
};

// ---------------- PTX helpers (base sm_103 target, no 'a' features) ----------
__device__ __forceinline__ uint32_t smem_u32(const void* p) {
    uint32_t a;
    asm("{ .reg .u64 t; cvta.to.shared.u64 t, %1; cvt.u32.u64 %0, t; }" : "=r"(a) : "l"(p));
    return a;
}
__device__ __forceinline__ void cpa16(uint32_t s, const void* g) {
    asm volatile("cp.async.cg.shared.global [%0], [%1], 16;" :: "r"(s), "l"(g));
}
__device__ __forceinline__ void ldsm_x4(uint32_t* r, uint32_t addr) {
    asm volatile("ldmatrix.sync.aligned.m8n8.x4.shared.b16 {%0,%1,%2,%3}, [%4];"
                 : "=r"(r[0]), "=r"(r[1]), "=r"(r[2]), "=r"(r[3]) : "r"(addr));
}
__device__ __forceinline__ void mma16816h(float* d, const uint32_t* a, uint32_t b0, uint32_t b1) {
    asm volatile("mma.sync.aligned.m16n8k16.row.col.f32.f16.f16.f32 "
                 "{%0,%1,%2,%3}, {%4,%5,%6,%7}, {%8,%9}, {%0,%1,%2,%3};"
                 : "+f"(d[0]), "+f"(d[1]), "+f"(d[2]), "+f"(d[3])
                 : "r"(a[0]), "r"(a[1]), "r"(a[2]), "r"(a[3]), "r"(b0), "r"(b1));
}
// 64B-row tile swizzle: row r, byte-col kb in {0,16,32,48}.
__device__ __forceinline__ uint32_t taddr64(uint32_t base, int r, int kb) {
    return base + r * 64 + (kb ^ ((r << 3) & 48));
}

// ---------------- prep: normalize roi to int32 ----------------
__global__ void prep_roi_kernel(const void* __restrict__ roi_raw) {
    int i = blockIdx.x * blockDim.x + threadIdx.x;
    if (i >= NVR) return;
    const int* p32 = (const int*)roi_raw;
    bool is64 = true;
#pragma unroll
    for (int j = 0; j < 8; j++) is64 = is64 && (p32[2 * j + 1] == 0);
    g_roi[i] = is64 ? (int)((const long long*)roi_raw)[i] : p32[i];
}

// ---------------- pack w: g_wp[co][v] = w_l[c][roi[v]] ----------------
__global__ void pack_w_kernel(Params p) {
    int idx = blockIdx.x * 256 + threadIdx.x;
    int co = idx / NVR;
    int v = idx - co * NVR;
    int layer = (co >= 448) ? 3 : (co >= 192) ? 2 : (co >= 64) ? 1 : 0;
    int c = co - p.coff[layer];
    g_wp[idx] = p.w[layer][(size_t)c * NVT + g_roi[v]];
}

// ---------------- pack F: fp16 hi/lo split of fmap, K padded ----------------
__global__ void pack_F_kernel(Params p) {
    int e = blockIdx.x * 256 + threadIdx.x;
    int layer = (e >= 2981888) ? 3 : (e >= 2457600) ? 2 : (e >= 1605632) ? 1 : 0;
    int local = e - (int)p.Foff[layer];
    int Kp = p.Kpad[layer], K = p.K[layer];
    int m = local / Kp;
    int k = local - m * Kp;
    float v = (k < K) ? p.fmap[layer][(size_t)m * K + k] : 0.f;
    __half h = __float2half_rn(v);
    __half l = __float2half_rn(v - __half2float(h));
    g_Fh[e] = h;
    g_Fl[e] = l;
}

// ---------------- pack G: gather + lrelu + transpose -> fp16 ----------------
__global__ void pack_G_kernel(Params p) {
    __shared__ float s[64][132];
    __shared__ int roi_s[128];
    int bx = blockIdx.x;
    int layer = (bx >= 66) ? 3 : (bx >= 62) ? 2 : (bx >= 49) ? 1 : 0;
    const int ktst0 = (layer == 0) ? 0 : (layer == 1) ? 49 : (layer == 2) ? 62 : 66;
    int k0 = (bx - ktst0) * 64;
    int v0 = blockIdx.y * 128;
    int tid = threadIdx.x;
    if (tid < 128) roi_s[tid] = (v0 + tid < NVR) ? g_roi[v0 + tid] : 0;
    __syncthreads();
    int K = p.K[layer], Kp = p.Kpad[layer];
    const float* __restrict__ rf = p.rf[layer];
    int vl = tid & 127, kh = tid >> 7;
    int rv = roi_s[vl];
#pragma unroll
    for (int j = 0; j < 32; j++) {
        int kl = kh * 32 + j;
        int k = k0 + kl;
        float val = 0.f;
        if (k < K) {
            val = __ldg(rf + (size_t)k * NVT + rv);
            val = (val > 0.f) ? val : 0.01f * val;
        }
        s[kl][vl] = val;
    }
    __syncthreads();
    int vl2 = tid >> 1, kq = tid & 1;
    uint32_t hw[16];
#pragma unroll
    for (int jj = 0; jj < 16; jj++) {
        float x0 = s[kq * 32 + 2 * jj][vl2];
        float x1 = s[kq * 32 + 2 * jj + 1][vl2];
        __half h0 = __float2half_rn(x0);
        __half h1 = __float2half_rn(x1);
        hw[jj] = (uint32_t)__half_as_ushort(h0) | ((uint32_t)__half_as_ushort(h1) << 16);
    }
    size_t base = p.Goff[layer] + (size_t)(v0 + vl2) * Kp + k0 + kq * 32;
    uint4* dh = reinterpret_cast<uint4*>(g_G + base);
#pragma unroll
    for (int q = 0; q < 4; q++)
        dh[q] = make_uint4(hw[4 * q], hw[4 * q + 1], hw[4 * q + 2], hw[4 * q + 3]);
}

// ---------------- mma.sync GEMM ----------------
// CTA tile: 128 ch (M) x 128 vox (N) x 32 (K-chunk), 8 warps (4m x 2n), warp
// tile 32x64. 2-term fp16: D += Fh*G + Fl*G. 4-stage cp.async pipeline,
// 2 CTAs/SM. smem: 4 stages x (Fh|Fl|G, 8KB each) = 96KB.
#define GEMM_SMEM 98304

__global__ __launch_bounds__(256, 2) void gemm_mma(Params p, float* __restrict__ out) {
    extern __shared__ __align__(128) char smem[];
    const uint32_t sb = smem_u32(smem);
    const int tid = threadIdx.x;
    const int wid = tid >> 5, lid = tid & 31;
    const int warp_m = wid & 3, warp_n = wid >> 2;

    const int my = blockIdx.x;                     // m-tile fastest: L2-friendly
    const int vt = blockIdx.y;
    const int layer = (my >= 28) ? 3 : (my >= 12) ? 2 : (my >= 4) ? 1 : 0;
    const int m0 = (my - p.mstart[layer]) * 128;
    const int v0 = vt * 128;
    const size_t goff = p.Goff[layer];
    const size_t foff = p.Foff[layer];
    const int Kp = p.Kpad[layer];
    const int nch = p.nch[layer];                  // Kpad/32

    const __half* __restrict__ aFh = g_Fh + foff + (size_t)m0 * Kp;
    const __half* __restrict__ aFl = g_Fl + foff + (size_t)m0 * Kp;
    const __half* __restrict__ aG  = g_G  + goff + (size_t)v0 * Kp;

    // 6 x 16B per thread per stage: arr(0:Fh 1:Fl 2:G), row, quad
    auto load_chunk = [&](int stage, int k0) {
        uint32_t sbase = sb + stage * 24576;
#pragma unroll
        for (int i = 0; i < 6; i++) {
            int flat = (i << 8) + tid;
            int arr = flat >> 9;
            int r = (flat >> 2) & 127;
            int q = flat & 3;
            const __half* src;
            if (arr == 0)      src = aFh + (size_t)r * Kp + k0 + q * 8;
            else if (arr == 1) src = aFl + (size_t)r * Kp + k0 + q * 8;
            else               src = aG  + (size_t)r * Kp + k0 + q * 8;
            cpa16(sbase + arr * 8192 + r * 64 + ((q * 16) ^ ((r << 3) & 48)), src);
        }
        asm volatile("cp.async.commit_group;" ::: "memory");
    };

    float d[2][8][4];
#pragma unroll
    for (int i = 0; i < 2; i++)
#pragma unroll
        for (int j = 0; j < 8; j++)
#pragma unroll
            for (int q = 0; q < 4; q++) d[i][j][q] = 0.f;

    const int frow = ((lid >> 3) & 1) * 8 + (lid & 7);
    const int fkb = (lid >> 4) * 16;

    if (0 < nch) load_chunk(0, 0);
    if (1 < nch) load_chunk(1, 32);
    if (2 < nch) load_chunk(2, 64);

    for (int c = 0; c < nch; c++) {
        if (c + 3 <= nch)      asm volatile("cp.async.wait_group 2;" ::: "memory");
        else if (c + 2 == nch) asm volatile("cp.async.wait_group 1;" ::: "memory");
        else                   asm volatile("cp.async.wait_group 0;" ::: "memory");
        __syncthreads();
        if (c + 3 < nch) load_chunk((c + 3) & 3, (c + 3) * 32);

        const int stage = c & 3;
        const uint32_t Fh = sb + stage * 24576;
        const uint32_t Fl = Fh + 8192;
        const uint32_t G  = Fh + 16384;

#pragma unroll
        for (int ks = 0; ks < 2; ks++) {
            const int kb = ks * 32 + fkb;
            uint32_t ah[2][4], al[2][4], b[4][4];
#pragma unroll
            for (int mf = 0; mf < 2; mf++) {
                int r = warp_m * 32 + mf * 16 + frow;
                ldsm_x4(ah[mf], taddr64(Fh, r, kb));
                ldsm_x4(al[mf], taddr64(Fl, r, kb));
            }
#pragma unroll
            for (int pr = 0; pr < 4; pr++) {
                int r = warp_n * 64 + pr * 16 + frow;
                ldsm_x4(b[pr], taddr64(G, r, kb));
            }
#pragma unroll
            for (int mf = 0; mf < 2; mf++)
#pragma unroll
                for (int nf = 0; nf < 8; nf++) {
                    const int pr = nf >> 1, s = nf & 1;
                    mma16816h(d[mf][nf], ah[mf], b[pr][s], b[pr][2 + s]);
                    mma16816h(d[mf][nf], al[mf], b[pr][s], b[pr][2 + s]);
                }
        }
    }

    // ---- epilogue: scale by g_wp, float2 stores ----
    const int Cm = p.Cmask[layer], Cs = p.Csh[layer], co0 = p.coff[layer];
    const int vbase = v0 + warp_n * 64 + (lid & 3) * 2;
#pragma unroll
    for (int mf = 0; mf < 2; mf++) {
        const int mrow = m0 + warp_m * 32 + mf * 16 + (lid >> 2);
#pragma unroll
        for (int half = 0; half < 2; half++) {
            const int m = mrow + half * 8;
            const int cch = m & Cm;
            const int b = m >> Cs;
            const int co = co0 + cch;
            const float* wrow = g_wp + (size_t)co * NVR;
            float* orow = out + ((size_t)(b * COUT + co)) * NVR;
#pragma unroll
            for (int nf = 0; nf < 8; nf++) {
                const int v = vbase + nf * 8;
                if (v < NVR) {
                    float2 wp = *reinterpret_cast<const float2*>(wrow + v);
                    float2 o;
                    o.x = d[mf][nf][half * 2 + 0] * wp.x;
                    o.y = d[mf][nf][half * 2 + 1] * wp.y;
                    *reinterpret_cast<float2*>(orow + v) = o;
                }
            }
        }
    }
}

// ---------------- host ----------------
extern "C" void kernel_launch(void* const* d_in, const int* in_sizes, int n_in,
                              void* d_out, int out_size)
{
    static const int FM[4] = {1605632, 802816, 401408, 200704};
    static const int RFS[4] = {62720000, 15680000, 3920000, 980000};
    static const int WS[4] = {1280000, 2560000, 5120000, 10240000};

    Params p;
    const void* roi = nullptr;
    for (int i = 0; i < n_in; i++) {
        int n = in_sizes[i];
        for (int l = 0; l < 4; l++) {
            if (n == FM[l])  p.fmap[l] = (const float*)d_in[i];
            if (n == RFS[l]) p.rf[l]   = (const float*)d_in[i];
            if (n == WS[l])  p.w[l]    = (const float*)d_in[i];
        }
        if (n == NVR) roi = d_in[i];
    }

    const int Ks[4]   = {3136, 784, 196, 49};
    const int Kps[4]  = {3136, 832, 256, 64};
    const int Cs[4]   = {64, 128, 256, 512};
    const int Csh[4]  = {6, 7, 8, 9};
    size_t go = 0, fo = 0;
    int coff = 0, ms = 0;
    for (int l = 0; l < 4; l++) {
        p.K[l] = Ks[l];
        p.Kpad[l] = Kps[l];
        p.nch[l] = Kps[l] / 32;
        p.Cmask[l] = Cs[l] - 1;
        p.Csh[l] = Csh[l];
        p.coff[l] = coff; coff += Cs[l];
        p.mstart[l] = ms; ms += (8 * Cs[l]) / 128;   // 4, 8, 16, 32 -> 60 m-tiles
        p.Goff[l] = go;  go += (size_t)8064 * Kps[l];
        p.Foff[l] = fo;  fo += (size_t)(8 * Cs[l]) * Kps[l];
    }

    prep_roi_kernel<<<32, 256>>>(roi);
    pack_w_kernel<<<COUT * NVR / 256, 256>>>(p);
    pack_F_kernel<<<3244032 / 256, 256>>>(p);
    pack_G_kernel<<<dim3(67, 63), 256>>>(p);

    cudaFuncSetAttribute(gemm_mma, cudaFuncAttributeMaxDynamicSharedMemorySize, GEMM_SMEM);
    gemm_mma<<<dim3(60, 63), 256, GEMM_SMEM>>>(p, (float*)d_out);
}